// round 1
// baseline (speedup 1.0000x reference)
#include <cuda_runtime.h>
#include <math.h>

#define MTILE   64
#define KC      64
#define THREADS 256
#define W2PAD   260   // padded row stride (floats) for transposed w2 chunk

// dynamic shared layout (floats):
//  sX   : MTILE*3      = 192
//  sW1  : 256*3        = 768
//  sB1  : 256
//  sB2  : 256
//  sW3  : 3*256        = 768
//  sB3  : 4
//  sH1  : MTILE*256    = 16384
//  sW2c : KC*W2PAD     = 16640
static const int SMEM_FLOATS = 192 + 768 + 256 + 256 + 768 + 4 + MTILE * 256 + KC * W2PAD;

__global__ __launch_bounds__(THREADS, 1)
void dpl_mlp_kernel(const float* __restrict__ x,
                    const float* __restrict__ w1,
                    const float* __restrict__ b1,
                    const float* __restrict__ w2,
                    const float* __restrict__ b2,
                    const float* __restrict__ w3,
                    const float* __restrict__ b3,
                    float* __restrict__ out,
                    int Btot, int write_logits)
{
    extern __shared__ float sm[];
    float* sX  = sm;                  // 192
    float* sW1 = sX  + MTILE * 3;     // 768
    float* sB1 = sW1 + 768;           // 256
    float* sB2 = sB1 + 256;           // 256
    float* sW3 = sB2 + 256;           // 768
    float* sB3 = sW3 + 768;           // 4
    float* sH1 = sB3 + 4;             // MTILE*256
    float* sW2 = sH1 + MTILE * 256;   // KC*W2PAD

    const int tid = threadIdx.x;
    const int row0 = blockIdx.x * MTILE;

    // ---- stage parameters ----
    for (int i = tid; i < 768; i += THREADS) sW1[i] = w1[i];
    for (int i = tid; i < 256; i += THREADS) { sB1[i] = b1[i]; sB2[i] = b2[i]; }
    for (int i = tid; i < 768; i += THREADS) sW3[i] = w3[i];
    if (tid < 3) sB3[tid] = b3[tid];

    // ---- stage x tile ----
    for (int i = tid; i < MTILE * 3; i += THREADS) {
        long g = (long)row0 * 3 + i;
        sX[i] = (g < (long)Btot * 3) ? x[g] : 0.0f;
    }
    __syncthreads();

    // ---- layer 1: thread t computes column j = t for all MTILE rows ----
    {
        const float a0 = sW1[tid * 3 + 0];
        const float a1 = sW1[tid * 3 + 1];
        const float a2 = sW1[tid * 3 + 2];
        const float bb = sB1[tid];
        #pragma unroll 8
        for (int r = 0; r < MTILE; r++) {
            float v = fmaf(sX[r * 3 + 0], a0,
                      fmaf(sX[r * 3 + 1], a1,
                      fmaf(sX[r * 3 + 2], a2, bb)));
            sH1[r * 256 + tid] = fmaxf(v, 0.0f);
        }
    }
    __syncthreads();

    // ---- layer 2: 64x256 output tile, thread (ty,tx): rows ty*4..+3, cols {jj*64 + tx*4 + q} ----
    const int ty = tid >> 4;   // 0..15
    const int tx = tid & 15;   // 0..15

    float acc[4][16];
    #pragma unroll
    for (int rr = 0; rr < 4; rr++)
        #pragma unroll
        for (int q = 0; q < 16; q++) acc[rr][q] = 0.0f;

    for (int kc = 0; kc < 256; kc += KC) {
        // load w2 chunk transposed: sW2[kk*W2PAD + j] = w2[j*256 + kc + kk]
        {
            const int kk = tid & 63;
            const int j0 = tid >> 6;   // 0..3
            #pragma unroll 8
            for (int i = 0; i < 64; i++) {
                const int j = j0 + 4 * i;
                sW2[kk * W2PAD + j] = w2[j * 256 + kc + kk];
            }
        }
        __syncthreads();

        const float* hbase = &sH1[(ty * 4) * 256 + kc];
        #pragma unroll 2
        for (int kk4 = 0; kk4 < KC; kk4 += 4) {
            float4 hv0 = *(const float4*)&hbase[0 * 256 + kk4];
            float4 hv1 = *(const float4*)&hbase[1 * 256 + kk4];
            float4 hv2 = *(const float4*)&hbase[2 * 256 + kk4];
            float4 hv3 = *(const float4*)&hbase[3 * 256 + kk4];
            float hr[4][4] = {
                {hv0.x, hv0.y, hv0.z, hv0.w},
                {hv1.x, hv1.y, hv1.z, hv1.w},
                {hv2.x, hv2.y, hv2.z, hv2.w},
                {hv3.x, hv3.y, hv3.z, hv3.w}
            };
            #pragma unroll
            for (int u = 0; u < 4; u++) {
                #pragma unroll
                for (int jj = 0; jj < 4; jj++) {
                    float4 wv = *(const float4*)&sW2[(kk4 + u) * W2PAD + jj * 64 + tx * 4];
                    acc[0][jj*4+0] = fmaf(hr[0][u], wv.x, acc[0][jj*4+0]);
                    acc[0][jj*4+1] = fmaf(hr[0][u], wv.y, acc[0][jj*4+1]);
                    acc[0][jj*4+2] = fmaf(hr[0][u], wv.z, acc[0][jj*4+2]);
                    acc[0][jj*4+3] = fmaf(hr[0][u], wv.w, acc[0][jj*4+3]);
                    acc[1][jj*4+0] = fmaf(hr[1][u], wv.x, acc[1][jj*4+0]);
                    acc[1][jj*4+1] = fmaf(hr[1][u], wv.y, acc[1][jj*4+1]);
                    acc[1][jj*4+2] = fmaf(hr[1][u], wv.z, acc[1][jj*4+2]);
                    acc[1][jj*4+3] = fmaf(hr[1][u], wv.w, acc[1][jj*4+3]);
                    acc[2][jj*4+0] = fmaf(hr[2][u], wv.x, acc[2][jj*4+0]);
                    acc[2][jj*4+1] = fmaf(hr[2][u], wv.y, acc[2][jj*4+1]);
                    acc[2][jj*4+2] = fmaf(hr[2][u], wv.z, acc[2][jj*4+2]);
                    acc[2][jj*4+3] = fmaf(hr[2][u], wv.w, acc[2][jj*4+3]);
                    acc[3][jj*4+0] = fmaf(hr[3][u], wv.x, acc[3][jj*4+0]);
                    acc[3][jj*4+1] = fmaf(hr[3][u], wv.y, acc[3][jj*4+1]);
                    acc[3][jj*4+2] = fmaf(hr[3][u], wv.z, acc[3][jj*4+2]);
                    acc[3][jj*4+3] = fmaf(hr[3][u], wv.w, acc[3][jj*4+3]);
                }
            }
        }
        __syncthreads();
    }

    // ---- epilogue: relu(+b2), layer3 partial dot products ----
    float part[4][3];
    #pragma unroll
    for (int rr = 0; rr < 4; rr++) { part[rr][0] = 0.f; part[rr][1] = 0.f; part[rr][2] = 0.f; }

    #pragma unroll
    for (int jj = 0; jj < 4; jj++) {
        #pragma unroll
        for (int q = 0; q < 4; q++) {
            const int j = jj * 64 + tx * 4 + q;
            const float c0 = sW3[0 * 256 + j];
            const float c1 = sW3[1 * 256 + j];
            const float c2 = sW3[2 * 256 + j];
            const float bb = sB2[j];
            #pragma unroll
            for (int rr = 0; rr < 4; rr++) {
                float h = fmaxf(acc[rr][jj * 4 + q] + bb, 0.0f);
                part[rr][0] = fmaf(h, c0, part[rr][0]);
                part[rr][1] = fmaf(h, c1, part[rr][1]);
                part[rr][2] = fmaf(h, c2, part[rr][2]);
            }
        }
    }

    // reduce across the 16 tx lanes (xor 8..1 stays within each 16-lane half)
    #pragma unroll
    for (int rr = 0; rr < 4; rr++)
        #pragma unroll
        for (int c = 0; c < 3; c++) {
            float v = part[rr][c];
            v += __shfl_xor_sync(0xffffffffu, v, 8);
            v += __shfl_xor_sync(0xffffffffu, v, 4);
            v += __shfl_xor_sync(0xffffffffu, v, 2);
            v += __shfl_xor_sync(0xffffffffu, v, 1);
            part[rr][c] = v;
        }

    if (tx == 0) {
        const int r0 = row0 + ty * 4;
        float predbuf[8];
        float logitbuf[12];
        const float eps  = 1e-5f;
        const float norm = 1.0f / (1.0f + 2.0f * eps);
        #pragma unroll
        for (int rr = 0; rr < 4; rr++) {
            float z0 = part[rr][0] + sB3[0];
            float z1 = part[rr][1] + sB3[1];
            float z2 = part[rr][2] + sB3[2];
            logitbuf[rr * 3 + 0] = z0;
            logitbuf[rr * 3 + 1] = z1;
            logitbuf[rr * 3 + 2] = z2;

            float s0 = 1.0f / (1.0f + expf(-z0));
            float s1 = 1.0f / (1.0f + expf(-z1));
            float s2 = 1.0f / (1.0f + expf(-z2));
            float pp0 = (s0 + eps) * norm, pn0 = (1.0f - s0 + eps) * norm;
            float pp1 = (s1 + eps) * norm, pn1 = (1.0f - s1 + eps) * norm;
            float pp2 = (s2 + eps) * norm, pn2 = (1.0f - s2 + eps) * norm;

            // odd-parity terms of the (2,2,2) einsum
            float pred1 = pn0 * pn1 * pp2
                        + pn0 * pp1 * pn2
                        + pp0 * pn1 * pn2
                        + pp0 * pp1 * pp2;
            float pred0 = 1.0f - pred1;
            const float onorm = 1.0f / 1.002f;
            predbuf[rr * 2 + 0] = (pred0 + 0.001f) * onorm;
            predbuf[rr * 2 + 1] = (pred1 + 0.001f) * onorm;
        }
        if (r0 + 3 < Btot) {
            // pred: 8 consecutive floats at r0*2 (32B aligned); logitC: 12 consecutive at 2B+r0*3 (48B aligned)
            float4* po = (float4*)&out[(size_t)r0 * 2];
            po[0] = *(float4*)&predbuf[0];
            po[1] = *(float4*)&predbuf[4];
            if (write_logits) {
                float4* lo = (float4*)&out[(size_t)2 * Btot + (size_t)r0 * 3];
                lo[0] = *(float4*)&logitbuf[0];
                lo[1] = *(float4*)&logitbuf[4];
                lo[2] = *(float4*)&logitbuf[8];
            }
        } else {
            #pragma unroll
            for (int rr = 0; rr < 4; rr++) {
                int r = r0 + rr;
                if (r < Btot) {
                    out[(size_t)r * 2 + 0] = predbuf[rr * 2 + 0];
                    out[(size_t)r * 2 + 1] = predbuf[rr * 2 + 1];
                    if (write_logits) {
                        out[(size_t)2 * Btot + (size_t)r * 3 + 0] = logitbuf[rr * 3 + 0];
                        out[(size_t)2 * Btot + (size_t)r * 3 + 1] = logitbuf[rr * 3 + 1];
                        out[(size_t)2 * Btot + (size_t)r * 3 + 2] = logitbuf[rr * 3 + 2];
                    }
                }
            }
        }
    }
}

extern "C" void kernel_launch(void* const* d_in, const int* in_sizes, int n_in,
                              void* d_out, int out_size)
{
    const float* x  = (const float*)d_in[0];
    const float* w1 = (const float*)d_in[1];
    const float* b1 = (const float*)d_in[2];
    const float* w2 = (const float*)d_in[3];
    const float* b2 = (const float*)d_in[4];
    const float* w3 = (const float*)d_in[5];
    const float* b3 = (const float*)d_in[6];
    float* out = (float*)d_out;

    const int B = in_sizes[0] / 3;
    const int write_logits = (out_size >= 5 * B) ? 1 : 0;

    const int smem_bytes = SMEM_FLOATS * (int)sizeof(float);
    cudaFuncSetAttribute(dpl_mlp_kernel,
                         cudaFuncAttributeMaxDynamicSharedMemorySize, smem_bytes);

    const int grid = (B + MTILE - 1) / MTILE;
    dpl_mlp_kernel<<<grid, THREADS, smem_bytes>>>(x, w1, b1, w2, b2, w3, b3,
                                                  out, B, write_logits);
}

// round 4
// speedup vs baseline: 3.4231x; 3.4231x over previous
#include <cuda_runtime.h>
#include <cuda_bf16.h>
#include <cstdint>
#include <cstddef>
#include <math.h>

#define THREADS 512
#define MROWS   128

// smem byte offsets (dynamic)
#define OFF_X     0        // 128*3*4 = 1536
#define OFF_W1P   1536     // 256*16  = 4096
#define OFF_WC    5632     // 256*16  = 4096
#define OFF_ZP    9728     // 4*128*16 = 8192
#define OFF_AHI   18432    // 128*512 = 65536
#define OFF_ALO   83968    // 65536
#define OFF_B     149504   // 2 bufs * (hi 20480 + lo 20480) = 81920
#define BCHUNK    20480    // 256 rows * 80 B
#define BBUF      40960
#define SMEM_TOTAL 231424

__device__ __nv_bfloat16 g_w2hi[65536];
__device__ __nv_bfloat16 g_w2lo[65536];

__device__ __forceinline__ void cp_async16(void* dst, const void* src) {
    uint32_t d;
    asm("{ .reg .u64 t; cvta.to.shared.u64 t, %1; cvt.u32.u64 %0, t; }" : "=r"(d) : "l"(dst));
    asm volatile("cp.async.cg.shared.global [%0], [%1], 16;" :: "r"(d), "l"(src) : "memory");
}
__device__ __forceinline__ void cp_commit() { asm volatile("cp.async.commit_group;" ::: "memory"); }
__device__ __forceinline__ void cp_wait1()  { asm volatile("cp.async.wait_group 1;" ::: "memory"); }
__device__ __forceinline__ void cp_wait0()  { asm volatile("cp.async.wait_group 0;" ::: "memory"); }

__device__ __forceinline__ void mma_bf16(float* d, const uint32_t* a, uint32_t b0, uint32_t b1) {
    asm volatile(
        "mma.sync.aligned.m16n8k16.row.col.f32.bf16.bf16.f32 "
        "{%0,%1,%2,%3}, {%4,%5,%6,%7}, {%8,%9}, {%0,%1,%2,%3};"
        : "+f"(d[0]), "+f"(d[1]), "+f"(d[2]), "+f"(d[3])
        : "r"(a[0]), "r"(a[1]), "r"(a[2]), "r"(a[3]), "r"(b0), "r"(b1));
}

// ---------------- pre-kernel: split w2 into bf16 hi/lo ----------------
__global__ void w2_split_kernel(const float* __restrict__ w2) {
    int i = blockIdx.x * 256 + threadIdx.x;
    float v = w2[i];
    __nv_bfloat16 hp = __float2bfloat16(v);
    g_w2hi[i] = hp;
    g_w2lo[i] = __float2bfloat16(v - __bfloat162float(hp));
}

// ---------------- main fused kernel ----------------
__global__ __launch_bounds__(THREADS, 1)
void dpl_hmma_kernel(const float* __restrict__ x,
                     const float* __restrict__ w1,
                     const float* __restrict__ b1,
                     const float* __restrict__ b2,
                     const float* __restrict__ w3,
                     const float* __restrict__ b3,
                     float* __restrict__ out,
                     int Btot, int write_logits)
{
    extern __shared__ char smc[];
    const int tid  = threadIdx.x;
    const int wid  = tid >> 5;
    const int lane = tid & 31;
    const int row0 = blockIdx.x * MROWS;

    const int rg = wid & 3;        // row group: rows rg*32..+31
    const int cg = wid >> 2;       // col group: cols cg*64..+63
    const int g   = lane >> 2;     // 0..7
    const int tig = lane & 3;      // 0..3

    // ---- stage params + x ----
    {
        float* sX = (float*)(smc + OFF_X);
        for (int i = tid; i < MROWS * 3; i += THREADS) {
            long gi = (long)row0 * 3 + i;
            sX[i] = (gi < (long)Btot * 3) ? x[gi] : 0.0f;
        }
        if (tid < 256) {
            ((float4*)(smc + OFF_W1P))[tid] =
                make_float4(w1[tid*3+0], w1[tid*3+1], w1[tid*3+2], b1[tid]);
            ((float4*)(smc + OFF_WC))[tid] =
                make_float4(b2[tid], w3[tid], w3[256+tid], w3[512+tid]);
        }
    }
    __syncthreads();

    // ---- layer 1 -> A hi/lo bf16 tiles (XOR-swizzled, conflict-free) ----
    {
        const float*  sX   = (const float*)(smc + OFF_X);
        const float4* sW1P = (const float4*)(smc + OFF_W1P);
        const int rb = (wid & 3) * 32 + (lane & 7);
        const int jb = (wid >> 2) * 64 + ((lane >> 3) << 1);
        const uint32_t xorv = (uint32_t)((lane & 7) << 4);
        #pragma unroll
        for (int s = 0; s < 4; s++) {
            const int r = rb + s * 8;
            const float x0 = sX[r*3+0], x1 = sX[r*3+1], x2 = sX[r*3+2];
            char* rowhi = smc + OFF_AHI + r * 512;
            char* rowlo = smc + OFF_ALO + r * 512;
            #pragma unroll
            for (int t = 0; t < 8; t++) {
                const int j = jb + t * 8;
                float4 wa = sW1P[j];
                float4 wb = sW1P[j+1];
                float f0 = fmaf(x0, wa.x, fmaf(x1, wa.y, fmaf(x2, wa.z, wa.w)));
                float f1 = fmaf(x0, wb.x, fmaf(x1, wb.y, fmaf(x2, wb.z, wb.w)));
                f0 = fmaxf(f0, 0.0f); f1 = fmaxf(f1, 0.0f);
                __nv_bfloat16 h0 = __float2bfloat16(f0);
                __nv_bfloat16 h1 = __float2bfloat16(f1);
                __nv_bfloat162 hw; hw.x = h0; hw.y = h1;
                __nv_bfloat162 lw = __floats2bfloat162_rn(f0 - __bfloat162float(h0),
                                                          f1 - __bfloat162float(h1));
                const uint32_t off = (uint32_t)(j * 2) ^ xorv;
                *(uint32_t*)(rowhi + off) = *(uint32_t*)&hw;
                *(uint32_t*)(rowlo + off) = *(uint32_t*)&lw;
            }
        }
    }

    // ---- preload B chunk 0 (hi+lo) ----
    {
        #pragma unroll
        for (int it = 0; it < 4; it++) {
            int idx = tid + it * THREADS;       // 0..2047
            int mat = idx >> 10;                // 0 hi, 1 lo
            int n   = (idx >> 2) & 255;
            int gseg = idx & 3;
            const char* src = (const char*)(mat ? g_w2lo : g_w2hi)
                              + (size_t)n * 512 + gseg * 16;
            cp_async16(smc + OFF_B + mat * BCHUNK + n * 80 + gseg * 16, src);
        }
        cp_commit();
    }

    // ---- accumulators ----
    float acc[2][8][4];
    #pragma unroll
    for (int mt = 0; mt < 2; mt++)
        #pragma unroll
        for (int nt = 0; nt < 8; nt++)
            #pragma unroll
            for (int q = 0; q < 4; q++) acc[mt][nt][q] = 0.0f;

    const uint32_t axor = (uint32_t)(g << 4);
    const char* arow0hi = smc + OFF_AHI + (rg * 32 + g) * 512;
    const char* arow0lo = smc + OFF_ALO + (rg * 32 + g) * 512;

    // ---- main loop over 8 k-chunks of 32 ----
    for (int c = 0; c < 8; c++) {
        if (c < 7) {
            const int nxt = c + 1;
            #pragma unroll
            for (int it = 0; it < 4; it++) {
                int idx = tid + it * THREADS;
                int mat = idx >> 10;
                int n   = (idx >> 2) & 255;
                int gseg = idx & 3;
                const char* src = (const char*)(mat ? g_w2lo : g_w2hi)
                                  + (size_t)n * 512 + nxt * 64 + gseg * 16;
                cp_async16(smc + OFF_B + (nxt & 1) * BBUF + mat * BCHUNK + n * 80 + gseg * 16, src);
            }
            cp_commit();
            cp_wait1();
        } else {
            cp_wait0();
        }
        __syncthreads();

        const char* bb = smc + OFF_B + (c & 1) * BBUF;

        #pragma unroll
        for (int ks = 0; ks < 2; ks++) {
            const int kg = c * 32 + ks * 16;
            const uint32_t koffL = ((uint32_t)((kg + tig * 2) * 2)) ^ axor;
            const uint32_t koffH = ((uint32_t)((kg + tig * 2 + 8) * 2)) ^ axor;

            uint32_t ahi[2][4], alo[2][4];
            #pragma unroll
            for (int mt = 0; mt < 2; mt++) {
                const int ro = mt * 16 * 512;
                ahi[mt][0] = *(const uint32_t*)(arow0hi + ro + koffL);
                ahi[mt][1] = *(const uint32_t*)(arow0hi + ro + 8*512 + koffL);
                ahi[mt][2] = *(const uint32_t*)(arow0hi + ro + koffH);
                ahi[mt][3] = *(const uint32_t*)(arow0hi + ro + 8*512 + koffH);
                alo[mt][0] = *(const uint32_t*)(arow0lo + ro + koffL);
                alo[mt][1] = *(const uint32_t*)(arow0lo + ro + 8*512 + koffL);
                alo[mt][2] = *(const uint32_t*)(arow0lo + ro + koffH);
                alo[mt][3] = *(const uint32_t*)(arow0lo + ro + 8*512 + koffH);
            }

            const uint32_t bkL = (uint32_t)((ks * 16 + tig * 2) * 2);
            const uint32_t bkH = bkL + 16;
            #pragma unroll
            for (int nt = 0; nt < 8; nt++) {
                const int n = cg * 64 + nt * 8 + g;
                const char* brow = bb + n * 80;
                uint32_t bh0 = *(const uint32_t*)(brow + bkL);
                uint32_t bh1 = *(const uint32_t*)(brow + bkH);
                uint32_t bl0 = *(const uint32_t*)(brow + BCHUNK + bkL);
                uint32_t bl1 = *(const uint32_t*)(brow + BCHUNK + bkH);
                #pragma unroll
                for (int mt = 0; mt < 2; mt++) {
                    mma_bf16(acc[mt][nt], ahi[mt], bh0, bh1);
                    mma_bf16(acc[mt][nt], alo[mt], bh0, bh1);
                    mma_bf16(acc[mt][nt], ahi[mt], bl0, bl1);
                }
            }
        }
        __syncthreads();
    }

    // ---- epilogue: relu(+b2) + layer3 partials in registers ----
    const float4* sWC = (const float4*)(smc + OFF_WC);
    float z[4][3];
    #pragma unroll
    for (int i = 0; i < 4; i++) { z[i][0] = 0.f; z[i][1] = 0.f; z[i][2] = 0.f; }

    #pragma unroll
    for (int mt = 0; mt < 2; mt++) {
        #pragma unroll
        for (int nt = 0; nt < 8; nt++) {
            const int j0 = cg * 64 + nt * 8 + tig * 2;
            float4 wc0 = sWC[j0];
            float4 wc1 = sWC[j0 + 1];
            float h;
            h = fmaxf(acc[mt][nt][0] + wc0.x, 0.0f);
            z[mt*2][0] = fmaf(h, wc0.y, z[mt*2][0]);
            z[mt*2][1] = fmaf(h, wc0.z, z[mt*2][1]);
            z[mt*2][2] = fmaf(h, wc0.w, z[mt*2][2]);
            h = fmaxf(acc[mt][nt][1] + wc1.x, 0.0f);
            z[mt*2][0] = fmaf(h, wc1.y, z[mt*2][0]);
            z[mt*2][1] = fmaf(h, wc1.z, z[mt*2][1]);
            z[mt*2][2] = fmaf(h, wc1.w, z[mt*2][2]);
            h = fmaxf(acc[mt][nt][2] + wc0.x, 0.0f);
            z[mt*2+1][0] = fmaf(h, wc0.y, z[mt*2+1][0]);
            z[mt*2+1][1] = fmaf(h, wc0.z, z[mt*2+1][1]);
            z[mt*2+1][2] = fmaf(h, wc0.w, z[mt*2+1][2]);
            h = fmaxf(acc[mt][nt][3] + wc1.x, 0.0f);
            z[mt*2+1][0] = fmaf(h, wc1.y, z[mt*2+1][0]);
            z[mt*2+1][1] = fmaf(h, wc1.z, z[mt*2+1][1]);
            z[mt*2+1][2] = fmaf(h, wc1.w, z[mt*2+1][2]);
        }
    }
    // reduce across the 4 lanes of each quad
    #pragma unroll
    for (int i = 0; i < 4; i++)
        #pragma unroll
        for (int cmp = 0; cmp < 3; cmp++) {
            float v = z[i][cmp];
            v += __shfl_xor_sync(0xffffffffu, v, 1);
            v += __shfl_xor_sync(0xffffffffu, v, 2);
            z[i][cmp] = v;
        }

    if (tig == 0) {
        float4* sZP = (float4*)(smc + OFF_ZP);
        #pragma unroll
        for (int i = 0; i < 4; i++) {
            const int r = rg * 32 + (i >> 1) * 16 + (i & 1) * 8 + g;
            sZP[cg * 128 + r] = make_float4(z[i][0], z[i][1], z[i][2], 0.0f);
        }
    }
    __syncthreads();

    if (tid < MROWS) {
        const float4* sZP = (const float4*)(smc + OFF_ZP);
        float4 a0 = sZP[tid], a1 = sZP[128 + tid], a2 = sZP[256 + tid], a3 = sZP[384 + tid];
        float z0 = a0.x + a1.x + a2.x + a3.x + b3[0];
        float z1 = a0.y + a1.y + a2.y + a3.y + b3[1];
        float z2 = a0.z + a1.z + a2.z + a3.z + b3[2];

        const int gr = row0 + tid;
        if (gr < Btot) {
            const float eps  = 1e-5f;
            const float norm = 1.0f / (1.0f + 2.0f * eps);
            float s0 = 1.0f / (1.0f + expf(-z0));
            float s1 = 1.0f / (1.0f + expf(-z1));
            float s2 = 1.0f / (1.0f + expf(-z2));
            float pp0 = (s0 + eps) * norm, pn0 = (1.0f - s0 + eps) * norm;
            float pp1 = (s1 + eps) * norm, pn1 = (1.0f - s1 + eps) * norm;
            float pp2 = (s2 + eps) * norm, pn2 = (1.0f - s2 + eps) * norm;
            float pred1 = pn0*pn1*pp2 + pn0*pp1*pn2 + pp0*pn1*pn2 + pp0*pp1*pp2;
            float pred0 = 1.0f - pred1;
            const float onorm = 1.0f / 1.002f;
            float2 pr = make_float2((pred0 + 0.001f) * onorm, (pred1 + 0.001f) * onorm);
            *(float2*)&out[(size_t)gr * 2] = pr;
            if (write_logits) {
                float* outLg = &out[(size_t)2 * Btot + (size_t)gr * 3];
                outLg[0] = z0; outLg[1] = z1; outLg[2] = z2;
            }
        }
    }
}

extern "C" void kernel_launch(void* const* d_in, const int* in_sizes, int n_in,
                              void* d_out, int out_size)
{
    const float* x  = (const float*)d_in[0];
    const float* w1 = (const float*)d_in[1];
    const float* b1 = (const float*)d_in[2];
    const float* w2 = (const float*)d_in[3];
    const float* b2 = (const float*)d_in[4];
    const float* w3 = (const float*)d_in[5];
    const float* b3 = (const float*)d_in[6];
    float* out = (float*)d_out;

    const int B = in_sizes[0] / 3;
    const int write_logits = (out_size >= 5 * B) ? 1 : 0;

    w2_split_kernel<<<256, 256>>>(w2);

    cudaFuncSetAttribute(dpl_hmma_kernel,
                         cudaFuncAttributeMaxDynamicSharedMemorySize, SMEM_TOTAL);

    const int grid = (B + MROWS - 1) / MROWS;
    dpl_hmma_kernel<<<grid, THREADS, SMEM_TOTAL>>>(x, w1, b1, b2, w3, b3,
                                                   out, B, write_logits);
}